// round 13
// baseline (speedup 1.0000x reference)
#include <cuda_runtime.h>
#include <math.h>
#include <stdint.h>

#define D_DIM 512
#define ROWB 544            // padded row: 512 fp8 + 32B aug chunk
#define K_CODES 4096
#define N_TOK 32768
#define NITEM 4096          // 512 m-tiles (64 rows) x 8 groups (512 codes each)

// fp8 quantization scales (validated R8-R12)
#define SX 32.0f
#define SW 131072.0f

// ---------------- device scratch (no allocations allowed) ----------------
__device__ int     g_indices[N_TOK];
__device__ int     g_counts[K_CODES];
__device__ float   g_wnorm[K_CODES];
__device__ float   g_xnorm[N_TOK];
__device__ uint8_t g_Xq[(size_t)N_TOK * ROWB];     // e4m3, padded rows
__device__ uint8_t g_Wq[(size_t)K_CODES * ROWB];   // e4m3, padded rows
__device__ uint2   g_cand32[(size_t)N_TOK * 128];  // per (token, st, wn, q): top-2 packed keys

// ---------------- PTX helpers ----------------
__device__ __forceinline__ uint32_t smem_to_u32(const void* p) {
    uint32_t a;
    asm("{ .reg .u64 t; cvta.to.shared.u64 t, %1; cvt.u32.u64 %0, t; }" : "=r"(a) : "l"(p));
    return a;
}
#define LDSM_X4(r0, r1, r2, r3, addr) \
    asm volatile("ldmatrix.sync.aligned.m8n8.x4.shared.b16 {%0,%1,%2,%3}, [%4];" \
        : "=r"(r0), "=r"(r1), "=r"(r2), "=r"(r3) : "r"(addr))
#define MMA16832_FP8(d, a, b0, b1) \
    asm volatile("mma.sync.aligned.m16n8k32.row.col.f32.e4m3.e4m3.f32 " \
        "{%0,%1,%2,%3},{%4,%5,%6,%7},{%8,%9},{%0,%1,%2,%3};" \
        : "+f"((d)[0]), "+f"((d)[1]), "+f"((d)[2]), "+f"((d)[3]) \
        : "r"((a)[0]), "r"((a)[1]), "r"((a)[2]), "r"((a)[3]), "r"(b0), "r"(b1))
#define CP_ASYNC16(dst, src) \
    asm volatile("cp.async.cg.shared.global [%0], [%1], 16;" :: "r"(dst), "l"(src))
#define CP_COMMIT() asm volatile("cp.async.commit_group;" ::: "memory")
#define CP_WAIT0()  asm volatile("cp.async.wait_group 0;" ::: "memory")

__device__ __forceinline__ uint16_t pack_e4m3x2(float hi, float lo) {
    uint16_t r;
    asm("cvt.rn.satfinite.e4m3x2.f32 %0, %1, %2;" : "=h"(r) : "f"(hi), "f"(lo));
    return r;
}

// dynamic smem layout for stage1 (bytes) — 106 KB per CTA, 2 CTAs/SM
#define S_A     0                      // 32 KB A main (64 x 512B, swizzled)
#define S_AUGA  32768                  // 2 KB A aug (64 x 32B)
#define S_B0    34816                  // 32 KB
#define S_B1    67584                  // 32 KB
#define S_AGB   100352                 // 8 KB B aug (256 x 32B), single buffer
#define S_TOT   108544

// ---------------- fused convert + norm + aug write ----------------
__global__ void cvtnorm_kernel(const float* __restrict__ src, int which, float scale) {
    extern __shared__ float s[];               // [64][513]
    int r0 = blockIdx.x * 64;
    const float4* g4 = (const float4*)(src + (size_t)r0 * D_DIM);
    for (int u = threadIdx.x; u < 64 * 128; u += 256) {
        int row = u >> 7, c4 = u & 127;
        float4 v = g4[(size_t)row * 128 + c4];
        float* p = s + row * 513 + c4 * 4;
        p[0] = v.x; p[1] = v.y; p[2] = v.z; p[3] = v.w;
    }
    __syncthreads();
    uint32_t* dst = (uint32_t*)(which ? (void*)g_Xq : (void*)g_Wq) + (size_t)r0 * (ROWB / 4);
    for (int i = threadIdx.x; i < 64 * 128; i += 256) {
        int row = i >> 7, c4 = i & 127;
        const float* p = s + row * 513 + c4 * 4;
        uint32_t lo = pack_e4m3x2(p[1] * scale, p[0] * scale);
        uint32_t hi = pack_e4m3x2(p[3] * scale, p[2] * scale);
        dst[(size_t)row * (ROWB / 4) + c4] = lo | (hi << 16);
    }
    // zero aug slots 1..7
    for (int i = threadIdx.x; i < 64 * 7; i += 256) {
        int row = i / 7, j = i % 7;
        dst[(size_t)row * (ROWB / 4) + 128 + 1 + j] = 0;
    }
    // exact sequential norm per row (validated R3) + aug slot0
    // byte0: X=16 (0x58) / W=-wn*2^17 ; byte1: both 256 (0x78) -> +65536 bias per acc
    if (threadIdx.x < 64) {
        const float* p = s + threadIdx.x * 513;
        float acc = 0.f;
        #pragma unroll 8
        for (int i = 0; i < D_DIM; i++)
            acc = __fadd_rn(acc, __fmul_rn(p[i], p[i]));
        uint32_t augw;
        if (which) { g_xnorm[r0 + threadIdx.x] = acc; augw = 0x58u | (0x78u << 8); }
        else {
            g_wnorm[r0 + threadIdx.x] = acc;
            augw = (uint32_t)(pack_e4m3x2(0.f, -acc * 131072.f) & 0xFFu) | (0x78u << 8);
        }
        dst[(size_t)threadIdx.x * (ROWB / 4) + 128] = augw;
    }
}

// ---------------- stage1 cp.async loaders (256 threads) ----------------
__device__ __forceinline__ void issue_main(uint32_t sb, int tid, int st, int kc, int buf) {
    const uint8_t* src = g_Wq + (size_t)(st * 256) * ROWB + kc * 128;
    uint32_t bufaddr = sb + (buf ? S_B1 : S_B0);
    #pragma unroll
    for (int i = 0; i < 8; i++) {
        int unit = i * 256 + tid;               // 2048 16B units
        int nrow = unit >> 3, u = unit & 7;
        uint32_t dst = bufaddr + nrow * 128 + ((u ^ (nrow & 7)) << 4);
        CP_ASYNC16(dst, src + (size_t)nrow * ROWB + u * 16);
    }
    CP_COMMIT();
}
__device__ __forceinline__ void issue_aug(uint32_t sb, int tid, int st) {
    const uint8_t* src = g_Wq + (size_t)(st * 256) * ROWB + 512;
    uint32_t bufaddr = sb + S_AGB;
    #pragma unroll
    for (int i = 0; i < 2; i++) {
        int unit = i * 256 + tid;               // 512 16B units
        int nrow = unit >> 1, u = unit & 1;
        CP_ASYNC16(bufaddr + nrow * 32 + u * 16, src + (size_t)nrow * ROWB + u * 16);
    }
    CP_COMMIT();
}

__global__ void __launch_bounds__(256, 2) stage1_kernel() {
    extern __shared__ char smem[];
    const uint32_t sb = smem_to_u32(smem);
    const int tid = threadIdx.x;
    const int lane = tid & 31;
    const int w = tid >> 5;                // 8 warps
    const int wm = w & 1, wn = w >> 1;     // warp tile: rows wm*32, cols wn*64
    const unsigned FULL = 0xffffffffu;

    // static balanced item split
    const int G = gridDim.x, cta = blockIdx.x;
    const int qq = NITEM / G, rr = NITEM - qq * G;
    const int start = cta * qq + (cta < rr ? cta : rr);
    const int count = qq + (cta < rr ? 1 : 0);

    // per-lane ldmatrix addressing, XOR-periodic precompute
    const int a_row = (lane & 7) + ((lane >> 3) & 1) * 8;
    const int a_kh  = (lane >> 4) & 1;
    uint32_t apre[2][4], a_aug[2];
    #pragma unroll
    for (int mt = 0; mt < 2; mt++) {
        int r = wm * 32 + mt * 16 + a_row;
        uint32_t base = sb + S_A + r * 512;
        int ax = r & 7;
        #pragma unroll
        for (int s = 0; s < 4; s++)
            apre[mt][s] = base + ((uint32_t)((s * 2 + a_kh) ^ ax) << 4);
        a_aug[mt] = sb + S_AUGA + r * 32 + a_kh * 16;
    }
    const int b_row_in = (lane & 7) + ((lane >> 4) & 1) * 8;
    const int b_kh     = (lane >> 3) & 1;
    uint32_t bofs[4][4], b_augoff[4];
    #pragma unroll
    for (int p = 0; p < 4; p++) {
        int nr = wn * 64 + p * 16 + b_row_in;
        int bx = nr & 7;
        #pragma unroll
        for (int s = 0; s < 4; s++)
            bofs[p][s] = nr * 128 + ((uint32_t)((s * 2 + b_kh) ^ bx) << 4);
        b_augoff[p] = nr * 32 + b_kh * 16;
    }
    const int tg = lane & 3, g8 = lane >> 2;

    int cur_m = -1;
    for (int itm = start; itm < start + count; itm++) {
        const int mt_tile = itm >> 3, grp = itm & 7;
        const int m0 = mt_tile * 64;
        const int st0 = grp * 2;

        // prologue main B chunk (overlaps A reload); aug issued inside loop after barrier
        issue_main(sb, tid, st0, 0, 0);

        if (mt_tile != cur_m) {
            cur_m = mt_tile;
            __syncthreads();           // all warps done reading previous A
            const uint8_t* Xr = g_Xq + (size_t)m0 * ROWB;
            #pragma unroll 4
            for (int ld = 0; ld < 8; ld++) {
                int unit = ld * 256 + tid;           // 2048 main 16B units
                int r = unit >> 5, u = unit & 31;
                uint4 v = *(const uint4*)(Xr + (size_t)r * ROWB + u * 16);
                *(uint4*)(smem + S_A + r * 512 + ((u ^ (r & 7)) << 4)) = v;
            }
            if (tid < 128) {
                int r = tid >> 1, u = tid & 1;
                uint4 v = *(const uint4*)(Xr + (size_t)r * ROWB + 512 + u * 16);
                *(uint4*)(smem + S_AUGA + r * 32 + u * 16) = v;
            }
            __syncthreads();
        }

        float acc[2][8][4];
        for (int ch = 0; ch < 8; ch++) {
            const int stl = ch >> 2;
            if ((ch & 3) == 0) {
                #pragma unroll
                for (int mt = 0; mt < 2; mt++)
                    #pragma unroll
                    for (int nt = 0; nt < 8; nt++)
                        #pragma unroll
                        for (int e = 0; e < 4; e++) acc[mt][nt][e] = 0.f;
            }
            CP_WAIT0();
            __syncthreads();
            // aug for this supertile: issued after barrier (previous aug fully consumed)
            if ((ch & 3) == 0) issue_aug(sb, tid, st0 + stl);
            if (ch + 1 < 8)
                issue_main(sb, tid, st0 + ((ch + 1) >> 2), (ch + 1) & 3, (ch + 1) & 1);
            const uint32_t bbuf = sb + ((ch & 1) ? S_B1 : S_B0);
            const uint32_t kadd = (uint32_t)(ch & 3) << 7;     // (ch&3)*128
            #pragma unroll
            for (int s = 0; s < 4; s++) {
                uint32_t a[2][4];
                #pragma unroll
                for (int mt = 0; mt < 2; mt++)
                    LDSM_X4(a[mt][0], a[mt][1], a[mt][2], a[mt][3], apre[mt][s] + kadd);
                #pragma unroll
                for (int p = 0; p < 4; p++) {
                    uint32_t r0, r1, r2, r3;
                    LDSM_X4(r0, r1, r2, r3, bbuf + bofs[p][s]);
                    MMA16832_FP8(acc[0][2 * p],     a[0], r0, r1);
                    MMA16832_FP8(acc[0][2 * p + 1], a[0], r2, r3);
                    MMA16832_FP8(acc[1][2 * p],     a[1], r0, r1);
                    MMA16832_FP8(acc[1][2 * p + 1], a[1], r2, r3);
                }
            }

            if ((ch & 3) == 3) {
                // ---- aug k-step: folds (65536 - wn*2^21) into acc ----
                // aug buffer completion guaranteed by CP_WAIT0 of chunks ch-2/ch-1
                uint32_t a[2][4];
                #pragma unroll
                for (int mt = 0; mt < 2; mt++)
                    LDSM_X4(a[mt][0], a[mt][1], a[mt][2], a[mt][3], a_aug[mt]);
                #pragma unroll
                for (int p = 0; p < 4; p++) {
                    uint32_t r0, r1, r2, r3;
                    LDSM_X4(r0, r1, r2, r3, sb + S_AGB + b_augoff[p]);
                    MMA16832_FP8(acc[0][2 * p],     a[0], r0, r1);
                    MMA16832_FP8(acc[0][2 * p + 1], a[0], r2, r3);
                    MMA16832_FP8(acc[1][2 * p],     a[1], r0, r1);
                    MMA16832_FP8(acc[1][2 * p + 1], a[1], r2, r3);
                }

                // ---- packed-key epilogue: top-2 (max) per 32-code quadrant ----
                // id (12 bits) == code: st<<8 | wn<<6 | q<<5 | nq<<3 | tg<<1 | e
                const int st = st0 + stl;
                const int idb0 = (st << 8) | (wn << 6) | (tg << 1);
                int v1[2][2][2], v2[2][2][2];    // [mt][h][q]
                #pragma unroll
                for (int mt = 0; mt < 2; mt++)
                    #pragma unroll
                    for (int h = 0; h < 2; h++)
                        #pragma unroll
                        for (int q = 0; q < 2; q++) {
                            v1[mt][h][q] = (int)0x80000000;
                            v2[mt][h][q] = (int)0x80000000;
                        }
                #pragma unroll
                for (int mt = 0; mt < 2; mt++)
                    #pragma unroll
                    for (int q = 0; q < 2; q++)
                        #pragma unroll
                        for (int nq = 0; nq < 4; nq++)
                            #pragma unroll
                            for (int h = 0; h < 2; h++)
                                #pragma unroll
                                for (int e = 0; e < 2; e++) {
                                    int id = idb0 | (q << 5) | (nq << 3) | e;
                                    int key = (__float_as_int(acc[mt][q * 4 + nq][h * 2 + e])
                                               & (int)0xFFFFF000) | id;
                                    int t = min(v1[mt][h][q], key);
                                    v1[mt][h][q] = max(v1[mt][h][q], key);
                                    v2[mt][h][q] = max(v2[mt][h][q], t);
                                }
                // merge sorted pairs across tg (offs 1,2) + direct store
                #pragma unroll
                for (int mt = 0; mt < 2; mt++)
                    #pragma unroll
                    for (int h = 0; h < 2; h++)
                        #pragma unroll
                        for (int q = 0; q < 2; q++) {
                            int V1 = v1[mt][h][q], V2 = v2[mt][h][q];
                            #pragma unroll
                            for (int off = 1; off <= 2; off <<= 1) {
                                int u1 = __shfl_xor_sync(FULL, V1, off);
                                int u2 = __shfl_xor_sync(FULL, V2, off);
                                int mn = min(V1, u1);
                                V1 = max(V1, u1);
                                V2 = max(mn, max(V2, u2));
                            }
                            if (tg == 0) {
                                int token = m0 + wm * 32 + mt * 16 + h * 8 + g8;
                                g_cand32[(size_t)token * 128 + st * 8 + wn * 2 + q] =
                                    make_uint2((uint32_t)V1, (uint32_t)V2);
                            }
                        }
            }
        }
    }
}

// ---------------- stage 2 (fused): top-8 of 256 + exact rescore + outputs ----------------
__global__ void __launch_bounds__(256) stage2_kernel(const float* __restrict__ X,
                                                     const float* __restrict__ W,
                                                     float* __restrict__ out_q,
                                                     float* __restrict__ out_loss,
                                                     float* __restrict__ out_idx,
                                                     int write_loss, int write_idx) {
    const int warp = threadIdx.x >> 5, lane = threadIdx.x & 31;
    const int token = blockIdx.x * 8 + warp;
    const unsigned FULL = 0xffffffffu;

    int k[8];
    #pragma unroll
    for (int j = 0; j < 4; j++) {
        uint2 c = g_cand32[(size_t)token * 128 + j * 32 + lane];
        k[2 * j]     = (int)c.x;
        k[2 * j + 1] = (int)c.y;
    }

    float xr[16];
    const float* x = X + (size_t)token * D_DIM;
    #pragma unroll
    for (int j = 0; j < 4; j++) {
        float4 v = *(const float4*)(x + j * 128 + lane * 4);
        xr[j * 4 + 0] = v.x; xr[j * 4 + 1] = v.y; xr[j * 4 + 2] = v.z; xr[j * 4 + 3] = v.w;
    }
    float xn = g_xnorm[token];
    float bd = 3.4e38f; int bi = 0x7fffffff;

    #pragma unroll
    for (int s = 0; s < 8; s++) {
        int lm = k[0];
        #pragma unroll
        for (int j = 1; j < 8; j++) lm = max(lm, k[j]);
        int m = lm;
        #pragma unroll
        for (int o = 16; o > 0; o >>= 1) m = max(m, __shfl_xor_sync(FULL, m, o));
        if (lm == m) {
            bool cns = false;
            #pragma unroll
            for (int j = 0; j < 8; j++)
                if (!cns && k[j] == m) { k[j] = (int)0x80000000; cns = true; }
        }
        int code = m & 0xFFF;

        const float* wv = W + (size_t)code * D_DIM;
        float acc = 0.f;
        #pragma unroll
        for (int j = 0; j < 4; j++) {
            float4 v = *(const float4*)(wv + j * 128 + lane * 4);
            acc = __fmaf_rn(xr[j * 4 + 0], v.x, acc);
            acc = __fmaf_rn(xr[j * 4 + 1], v.y, acc);
            acc = __fmaf_rn(xr[j * 4 + 2], v.z, acc);
            acc = __fmaf_rn(xr[j * 4 + 3], v.w, acc);
        }
        #pragma unroll
        for (int o = 16; o > 0; o >>= 1) acc += __shfl_xor_sync(FULL, acc, o);
        float dd = __fsub_rn(__fadd_rn(xn, g_wnorm[code]), 2.0f * acc);
        if (dd < bd || (dd == bd && code < bi)) { bd = dd; bi = code; }
    }

    // fused epilogue: quantized_st + loss + histogram (all lanes agree on bi)
    const float* wv = W + (size_t)bi * D_DIM;
    float s = 0.f;
    #pragma unroll
    for (int j = 0; j < 4; j++) {
        float4 qv = *(const float4*)(wv + j * 128 + lane * 4);
        float dx = __fsub_rn(qv.x, xr[j * 4 + 0]);
        float dy = __fsub_rn(qv.y, xr[j * 4 + 1]);
        float dz = __fsub_rn(qv.z, xr[j * 4 + 2]);
        float dw = __fsub_rn(qv.w, xr[j * 4 + 3]);
        float4 st;
        st.x = __fadd_rn(xr[j * 4 + 0], dx);
        st.y = __fadd_rn(xr[j * 4 + 1], dy);
        st.z = __fadd_rn(xr[j * 4 + 2], dz);
        st.w = __fadd_rn(xr[j * 4 + 3], dw);
        *(float4*)(out_q + (size_t)token * D_DIM + j * 128 + lane * 4) = st;
        s += dx * dx + dy * dy + dz * dz + dw * dw;
    }
    #pragma unroll
    for (int o = 16; o > 0; o >>= 1) s += __shfl_xor_sync(FULL, s, o);
    if (lane == 0) {
        g_indices[token] = bi;
        if (write_loss) out_loss[token] = 1.25f * s * (1.0f / D_DIM);
        if (write_idx)  out_idx[token] = (float)bi;
        atomicAdd(&g_counts[bi], 1);
    }
}

// ---------------- zero counts / perplexity ----------------
__global__ void zero_counts_kernel() {
    int i = blockIdx.x * blockDim.x + threadIdx.x;
    if (i < K_CODES) g_counts[i] = 0;
}
__global__ void perplexity_kernel(float* __restrict__ out_perp, int M) {
    __shared__ float ws[32];
    float inv = 1.0f / (float)M;
    float s = 0.f;
    for (int i = threadIdx.x; i < K_CODES; i += blockDim.x) {
        float p = (float)g_counts[i] * inv;
        s += p * logf(p + 1e-10f);
    }
    #pragma unroll
    for (int o = 16; o > 0; o >>= 1) s += __shfl_down_sync(0xffffffffu, s, o);
    if ((threadIdx.x & 31) == 0) ws[threadIdx.x >> 5] = s;
    __syncthreads();
    if (threadIdx.x == 0) {
        float tot = 0.f;
        int nw = blockDim.x >> 5;
        for (int w = 0; w < nw; w++) tot += ws[w];
        *out_perp = expf(-tot);
    }
}

// ---------------- launch ----------------
extern "C" void kernel_launch(void* const* d_in, const int* in_sizes, int n_in,
                              void* d_out, int out_size)
{
    const float* X = (const float*)d_in[0];   // flat_input [32768, 512]
    const float* W = (const float*)d_in[1];   // weight [4096, 512]
    const int M = in_sizes[0] / D_DIM;

    float* out = (float*)d_out;
    float* out_q = out;
    size_t base = (size_t)M * D_DIM;
    int has_loss = out_size >= (int)(base + M);
    int has_perp = out_size >= (int)(base + M + 1);
    int has_idx  = out_size >= (int)(base + 2 * M + 1);
    float* out_loss = out + base;
    float* out_perp = out_loss + M;
    float* out_idx  = out_perp + 1;

    int nsm = 148;
    cudaDeviceGetAttribute(&nsm, cudaDevAttrMultiProcessorCount, 0);
    if (nsm <= 0) nsm = 148;

    cudaFuncSetAttribute(stage1_kernel, cudaFuncAttributeMaxDynamicSharedMemorySize, S_TOT);
    cudaFuncSetAttribute(cvtnorm_kernel, cudaFuncAttributeMaxDynamicSharedMemorySize,
                         64 * 513 * 4);

    cvtnorm_kernel<<<M / 64, 256, 64 * 513 * 4>>>(X, 1, SX);       // X -> fp8 + xnorm + aug
    cvtnorm_kernel<<<K_CODES / 64, 256, 64 * 513 * 4>>>(W, 0, SW); // W -> fp8 + wnorm + aug
    zero_counts_kernel<<<(K_CODES + 255) / 256, 256>>>();
    stage1_kernel<<<2 * nsm, 256, S_TOT>>>();
    stage2_kernel<<<M / 8, 256>>>(X, W, out_q,
                                  has_loss ? out_loss : out_q,
                                  has_idx ? out_idx : out_q,
                                  has_loss, has_idx);
    if (has_perp) perplexity_kernel<<<1, 1024>>>(out_perp, M);
}

// round 15
// speedup vs baseline: 1.0077x; 1.0077x over previous
#include <cuda_runtime.h>
#include <math.h>
#include <stdint.h>

#define D_DIM 512
#define ROWB 544            // padded row: 512 fp8 + 32B aug chunk
#define K_CODES 4096
#define N_TOK 32768
#define NITEM 2048          // 256 m-tiles x 8 groups (512 codes each)

// fp8 quantization scales (validated R8-R13)
#define SX 32.0f
#define SW 131072.0f

// ---------------- device scratch (no allocations allowed) ----------------
__device__ int     g_indices[N_TOK];
__device__ int     g_counts[K_CODES];
__device__ float   g_wnorm[K_CODES];
__device__ float   g_xnorm[N_TOK];
__device__ uint8_t g_Xq[(size_t)N_TOK * ROWB];     // e4m3, padded rows
__device__ uint8_t g_Wq[(size_t)K_CODES * ROWB];   // e4m3, padded rows
__device__ uint2   g_cand32[(size_t)N_TOK * 128];  // per (token, st, wn, q): top-2 packed keys

// ---------------- PTX helpers ----------------
__device__ __forceinline__ uint32_t smem_to_u32(const void* p) {
    uint32_t a;
    asm("{ .reg .u64 t; cvta.to.shared.u64 t, %1; cvt.u32.u64 %0, t; }" : "=r"(a) : "l"(p));
    return a;
}
#define LDSM_X4(r0, r1, r2, r3, addr) \
    asm volatile("ldmatrix.sync.aligned.m8n8.x4.shared.b16 {%0,%1,%2,%3}, [%4];" \
        : "=r"(r0), "=r"(r1), "=r"(r2), "=r"(r3) : "r"(addr))
#define MMA16832_FP8(d, a, b0, b1) \
    asm volatile("mma.sync.aligned.m16n8k32.row.col.f32.e4m3.e4m3.f32 " \
        "{%0,%1,%2,%3},{%4,%5,%6,%7},{%8,%9},{%0,%1,%2,%3};" \
        : "+f"((d)[0]), "+f"((d)[1]), "+f"((d)[2]), "+f"((d)[3]) \
        : "r"((a)[0]), "r"((a)[1]), "r"((a)[2]), "r"((a)[3]), "r"(b0), "r"(b1))
#define CP_ASYNC16(dst, src) \
    asm volatile("cp.async.cg.shared.global [%0], [%1], 16;" :: "r"(dst), "l"(src))
#define CP_COMMIT() asm volatile("cp.async.commit_group;" ::: "memory")
#define CP_WAIT0()  asm volatile("cp.async.wait_group 0;" ::: "memory")

__device__ __forceinline__ uint16_t pack_e4m3x2(float hi, float lo) {
    uint16_t r;
    asm("cvt.rn.satfinite.e4m3x2.f32 %0, %1, %2;" : "=h"(r) : "f"(hi), "f"(lo));
    return r;
}

// dynamic smem layout for stage1 (bytes)
#define S_A     0                      // 64 KB A main (128 x 512B, swizzled)
#define S_AUGA  65536                  // 4 KB A aug (128 x 32B)
#define S_B0    (S_AUGA + 4096)        // 32 KB
#define S_B1    (S_B0 + 32768)         // 32 KB
#define S_AGB0  (S_B1 + 32768)         // 8 KB B aug (256 x 32B)
#define S_AGB1  (S_AGB0 + 8192)        // 8 KB
#define S_TOT   (S_AGB1 + 8192)        // 151552

// ---------------- fused convert + norm + aug write ----------------
__global__ void cvtnorm_kernel(const float* __restrict__ src, int which, float scale) {
    extern __shared__ float s[];               // [64][513]
    int r0 = blockIdx.x * 64;
    const float4* g4 = (const float4*)(src + (size_t)r0 * D_DIM);
    for (int u = threadIdx.x; u < 64 * 128; u += 256) {
        int row = u >> 7, c4 = u & 127;
        float4 v = g4[(size_t)row * 128 + c4];
        float* p = s + row * 513 + c4 * 4;
        p[0] = v.x; p[1] = v.y; p[2] = v.z; p[3] = v.w;
    }
    __syncthreads();
    uint32_t* dst = (uint32_t*)(which ? (void*)g_Xq : (void*)g_Wq) + (size_t)r0 * (ROWB / 4);
    for (int i = threadIdx.x; i < 64 * 128; i += 256) {
        int row = i >> 7, c4 = i & 127;
        const float* p = s + row * 513 + c4 * 4;
        uint32_t lo = pack_e4m3x2(p[1] * scale, p[0] * scale);
        uint32_t hi = pack_e4m3x2(p[3] * scale, p[2] * scale);
        dst[(size_t)row * (ROWB / 4) + c4] = lo | (hi << 16);
    }
    // zero aug slots 1..7
    for (int i = threadIdx.x; i < 64 * 7; i += 256) {
        int row = i / 7, j = i % 7;
        dst[(size_t)row * (ROWB / 4) + 128 + 1 + j] = 0;
    }
    // exact sequential norm per row (validated R3) + aug slot0
    // byte0: X=16 (0x58) / W=-wn*2^17 ; byte1: both 256 (0x78) -> +65536 bias per acc
    if (threadIdx.x < 64) {
        const float* p = s + threadIdx.x * 513;
        float acc = 0.f;
        #pragma unroll 8
        for (int i = 0; i < D_DIM; i++)
            acc = __fadd_rn(acc, __fmul_rn(p[i], p[i]));
        uint32_t augw;
        if (which) { g_xnorm[r0 + threadIdx.x] = acc; augw = 0x58u | (0x78u << 8); }
        else {
            g_wnorm[r0 + threadIdx.x] = acc;
            augw = (uint32_t)(pack_e4m3x2(0.f, -acc * 131072.f) & 0xFFu) | (0x78u << 8);
        }
        dst[(size_t)threadIdx.x * (ROWB / 4) + 128] = augw;
    }
}

// ---------------- stage1 cp.async loaders ----------------
__device__ __forceinline__ void issue_main(uint32_t sb, int tid, int st, int kc, int buf) {
    const uint8_t* src = g_Wq + (size_t)(st * 256) * ROWB + kc * 128;
    uint32_t bufaddr = sb + (buf ? S_B1 : S_B0);
    #pragma unroll
    for (int i = 0; i < 4; i++) {
        int unit = i * 512 + tid;               // 2048 16B units
        int nrow = unit >> 3, u = unit & 7;
        uint32_t dst = bufaddr + nrow * 128 + ((u ^ (nrow & 7)) << 4);
        CP_ASYNC16(dst, src + (size_t)nrow * ROWB + u * 16);
    }
    CP_COMMIT();
}
__device__ __forceinline__ void issue_aug(uint32_t sb, int tid, int st, int buf) {
    const uint8_t* src = g_Wq + (size_t)(st * 256) * ROWB + 512;
    uint32_t bufaddr = sb + (buf ? S_AGB1 : S_AGB0);
    int nrow = tid >> 1, u = tid & 1;
    CP_ASYNC16(bufaddr + nrow * 32 + u * 16, src + (size_t)nrow * ROWB + u * 16);
    CP_COMMIT();
}

__global__ void __launch_bounds__(512, 1) stage1_kernel() {
    extern __shared__ char smem[];
    const uint32_t sb = smem_to_u32(smem);
    const int tid = threadIdx.x;
    const int lane = tid & 31;
    const int w = tid >> 5;                // 16 warps
    const int wm = w & 3, wn = w >> 2;     // warp tile: rows wm*32, cols wn*64
    const unsigned FULL = 0xffffffffu;

    // static balanced item split
    const int G = gridDim.x, cta = blockIdx.x;
    const int qq = NITEM / G, rr = NITEM - qq * G;
    const int start = cta * qq + (cta < rr ? cta : rr);
    const int count = qq + (cta < rr ? 1 : 0);

    // per-lane ldmatrix addressing, XOR-periodic precompute
    const int a_row = (lane & 7) + ((lane >> 3) & 1) * 8;
    const int a_kh  = (lane >> 4) & 1;
    uint32_t apre[2][4], a_aug[2];
    #pragma unroll
    for (int mt = 0; mt < 2; mt++) {
        int r = wm * 32 + mt * 16 + a_row;
        uint32_t base = sb + S_A + r * 512;
        int ax = r & 7;
        #pragma unroll
        for (int s = 0; s < 4; s++)
            apre[mt][s] = base + ((uint32_t)((s * 2 + a_kh) ^ ax) << 4);
        a_aug[mt] = sb + S_AUGA + r * 32 + a_kh * 16;
    }
    const int b_row_in = (lane & 7) + ((lane >> 4) & 1) * 8;
    const int b_kh     = (lane >> 3) & 1;
    uint32_t bofs[4][4], b_augoff[4];
    #pragma unroll
    for (int p = 0; p < 4; p++) {
        int nr = wn * 64 + p * 16 + b_row_in;
        int bx = nr & 7;
        #pragma unroll
        for (int s = 0; s < 4; s++)
            bofs[p][s] = nr * 128 + ((uint32_t)((s * 2 + b_kh) ^ bx) << 4);
        b_augoff[p] = nr * 32 + b_kh * 16;
    }
    const int tg = lane & 3, g8 = lane >> 2;

    int cur_m = -1;
    for (int itm = start; itm < start + count; itm++) {
        const int mt_tile = itm >> 3, grp = itm & 7;
        const int m0 = mt_tile * 128;
        const int st0 = grp * 2;

        // prologue B for this item (overlaps A reload)
        issue_main(sb, tid, st0, 0, 0);
        issue_aug(sb, tid, st0, 0);

        if (mt_tile != cur_m) {
            cur_m = mt_tile;
            __syncthreads();
            const uint8_t* Xr = g_Xq + (size_t)m0 * ROWB;
            #pragma unroll 4
            for (int ld = 0; ld < 8; ld++) {
                int unit = ld * 512 + tid;
                int r = unit >> 5, u = unit & 31;
                uint4 v = *(const uint4*)(Xr + (size_t)r * ROWB + u * 16);
                *(uint4*)(smem + S_A + r * 512 + ((u ^ (r & 7)) << 4)) = v;
            }
            if (tid < 256) {
                int r = tid >> 1, u = tid & 1;
                uint4 v = *(const uint4*)(Xr + (size_t)r * ROWB + 512 + u * 16);
                *(uint4*)(smem + S_AUGA + r * 32 + u * 16) = v;
            }
            __syncthreads();
        }

        float acc[2][8][4];
        for (int ch = 0; ch < 8; ch++) {
            const int stl = ch >> 2;
            if ((ch & 3) == 0) {
                #pragma unroll
                for (int mt = 0; mt < 2; mt++)
                    #pragma unroll
                    for (int nt = 0; nt < 8; nt++)
                        #pragma unroll
                        for (int e = 0; e < 4; e++) acc[mt][nt][e] = 0.f;
            }
            CP_WAIT0();
            __syncthreads();
            if (ch + 1 < 8) {
                issue_main(sb, tid, st0 + ((ch + 1) >> 2), (ch + 1) & 3, (ch + 1) & 1);
                if (((ch + 1) & 3) == 0) issue_aug(sb, tid, st0 + 1, 1);
            }
            const uint32_t bbuf = sb + ((ch & 1) ? S_B1 : S_B0);
            const uint32_t kadd = (uint32_t)(ch & 3) << 7;     // (ch&3)*128
            #pragma unroll
            for (int s = 0; s < 4; s++) {
                uint32_t a[2][4];
                #pragma unroll
                for (int mt = 0; mt < 2; mt++)
                    LDSM_X4(a[mt][0], a[mt][1], a[mt][2], a[mt][3], apre[mt][s] + kadd);
                #pragma unroll
                for (int p = 0; p < 4; p++) {
                    uint32_t r0, r1, r2, r3;
                    LDSM_X4(r0, r1, r2, r3, bbuf + bofs[p][s]);
                    MMA16832_FP8(acc[0][2 * p],     a[0], r0, r1);
                    MMA16832_FP8(acc[0][2 * p + 1], a[0], r2, r3);
                    MMA16832_FP8(acc[1][2 * p],     a[1], r0, r1);
                    MMA16832_FP8(acc[1][2 * p + 1], a[1], r2, r3);
                }
            }

            if ((ch & 3) == 3) {
                // ---- aug k-step: folds (65536 - wn*2^21) into acc ----
                const uint32_t augb = sb + (stl ? S_AGB1 : S_AGB0);
                uint32_t a[2][4];
                #pragma unroll
                for (int mt = 0; mt < 2; mt++)
                    LDSM_X4(a[mt][0], a[mt][1], a[mt][2], a[mt][3], a_aug[mt]);
                #pragma unroll
                for (int p = 0; p < 4; p++) {
                    uint32_t r0, r1, r2, r3;
                    LDSM_X4(r0, r1, r2, r3, augb + b_augoff[p]);
                    MMA16832_FP8(acc[0][2 * p],     a[0], r0, r1);
                    MMA16832_FP8(acc[0][2 * p + 1], a[0], r2, r3);
                    MMA16832_FP8(acc[1][2 * p],     a[1], r0, r1);
                    MMA16832_FP8(acc[1][2 * p + 1], a[1], r2, r3);
                }

                // ---- packed-key epilogue: top-2 (max) per 32-code quadrant ----
                // id (12 bits) == code: st<<8 | wn<<6 | q<<5 | nq<<3 | tg<<1 | e
                const int st = st0 + stl;
                const int idb0 = (st << 8) | (wn << 6) | (tg << 1);
                int v1[2][2][2], v2[2][2][2];    // [mt][h][q]
                #pragma unroll
                for (int mt = 0; mt < 2; mt++)
                    #pragma unroll
                    for (int h = 0; h < 2; h++)
                        #pragma unroll
                        for (int q = 0; q < 2; q++) {
                            v1[mt][h][q] = (int)0x80000000;
                            v2[mt][h][q] = (int)0x80000000;
                        }
                #pragma unroll
                for (int mt = 0; mt < 2; mt++)
                    #pragma unroll
                    for (int q = 0; q < 2; q++)
                        #pragma unroll
                        for (int nq = 0; nq < 4; nq++)
                            #pragma unroll
                            for (int h = 0; h < 2; h++)
                                #pragma unroll
                                for (int e = 0; e < 2; e++) {
                                    int id = idb0 | (q << 5) | (nq << 3) | e;
                                    int key = (__float_as_int(acc[mt][q * 4 + nq][h * 2 + e])
                                               & (int)0xFFFFF000) | id;
                                    int t = min(v1[mt][h][q], key);
                                    v1[mt][h][q] = max(v1[mt][h][q], key);
                                    v2[mt][h][q] = max(v2[mt][h][q], t);
                                }
                // merge sorted pairs across tg (offs 1,2) + direct store
                #pragma unroll
                for (int mt = 0; mt < 2; mt++)
                    #pragma unroll
                    for (int h = 0; h < 2; h++)
                        #pragma unroll
                        for (int q = 0; q < 2; q++) {
                            int V1 = v1[mt][h][q], V2 = v2[mt][h][q];
                            #pragma unroll
                            for (int off = 1; off <= 2; off <<= 1) {
                                int u1 = __shfl_xor_sync(FULL, V1, off);
                                int u2 = __shfl_xor_sync(FULL, V2, off);
                                int mn = min(V1, u1);
                                V1 = max(V1, u1);
                                V2 = max(mn, max(V2, u2));
                            }
                            if (tg == 0) {
                                int token = m0 + wm * 32 + mt * 16 + h * 8 + g8;
                                g_cand32[(size_t)token * 128 + st * 8 + wn * 2 + q] =
                                    make_uint2((uint32_t)V1, (uint32_t)V2);
                            }
                        }
            }
        }
    }
}

// ---------------- stage 2 (fused): top-8 of 256, PARALLEL exact rescore + outputs ----------------
__global__ void __launch_bounds__(256) stage2_kernel(const float* __restrict__ X,
                                                     const float* __restrict__ W,
                                                     float* __restrict__ out_q,
                                                     float* __restrict__ out_loss,
                                                     float* __restrict__ out_idx,
                                                     int write_loss, int write_idx) {
    const int warp = threadIdx.x >> 5, lane = threadIdx.x & 31;
    const int token = blockIdx.x * 8 + warp;
    const unsigned FULL = 0xffffffffu;

    int k[8];
    #pragma unroll
    for (int j = 0; j < 4; j++) {
        uint2 c = g_cand32[(size_t)token * 128 + j * 32 + lane];
        k[2 * j]     = (int)c.x;
        k[2 * j + 1] = (int)c.y;
    }

    float xr[16];
    const float* x = X + (size_t)token * D_DIM;
    #pragma unroll
    for (int j = 0; j < 4; j++) {
        float4 v = *(const float4*)(x + j * 128 + lane * 4);
        xr[j * 4 + 0] = v.x; xr[j * 4 + 1] = v.y; xr[j * 4 + 2] = v.z; xr[j * 4 + 3] = v.w;
    }
    float xn = g_xnorm[token];

    // top-8 of 256 packed keys (validated depth; all codes distinct by construction)
    int cand[8];
    #pragma unroll
    for (int s = 0; s < 8; s++) {
        int lm = k[0];
        #pragma unroll
        for (int j = 1; j < 8; j++) lm = max(lm, k[j]);
        int m = lm;
        #pragma unroll
        for (int o = 16; o > 0; o >>= 1) m = max(m, __shfl_xor_sync(FULL, m, o));
        if (lm == m) {
            bool cns = false;
            #pragma unroll
            for (int j = 0; j < 8; j++)
                if (!cns && k[j] == m) { k[j] = (int)0x80000000; cns = true; }
        }
        cand[s] = m & 0xFFF;
    }

    // 8 exact fp32 dots, 2 batches of 4 PARALLEL accumulators (MLP=4 each)
    float accs[8];
    #pragma unroll
    for (int b = 0; b < 2; b++) {
        const float* w0 = W + (size_t)cand[b * 4 + 0] * D_DIM;
        const float* w1 = W + (size_t)cand[b * 4 + 1] * D_DIM;
        const float* w2 = W + (size_t)cand[b * 4 + 2] * D_DIM;
        const float* w3 = W + (size_t)cand[b * 4 + 3] * D_DIM;
        float a0 = 0.f, a1 = 0.f, a2 = 0.f, a3 = 0.f;
        #pragma unroll
        for (int j = 0; j < 4; j++) {
            int off = j * 128 + lane * 4;
            float4 v0 = *(const float4*)(w0 + off);
            float4 v1 = *(const float4*)(w1 + off);
            float4 v2 = *(const float4*)(w2 + off);
            float4 v3 = *(const float4*)(w3 + off);
            a0 = __fmaf_rn(xr[j*4+0], v0.x, a0); a0 = __fmaf_rn(xr[j*4+1], v0.y, a0);
            a0 = __fmaf_rn(xr[j*4+2], v0.z, a0); a0 = __fmaf_rn(xr[j*4+3], v0.w, a0);
            a1 = __fmaf_rn(xr[j*4+0], v1.x, a1); a1 = __fmaf_rn(xr[j*4+1], v1.y, a1);
            a1 = __fmaf_rn(xr[j*4+2], v1.z, a1); a1 = __fmaf_rn(xr[j*4+3], v1.w, a1);
            a2 = __fmaf_rn(xr[j*4+0], v2.x, a2); a2 = __fmaf_rn(xr[j*4+1], v2.y, a2);
            a2 = __fmaf_rn(xr[j*4+2], v2.z, a2); a2 = __fmaf_rn(xr[j*4+3], v2.w, a2);
            a3 = __fmaf_rn(xr[j*4+0], v3.x, a3); a3 = __fmaf_rn(xr[j*4+1], v3.y, a3);
            a3 = __fmaf_rn(xr[j*4+2], v3.z, a3); a3 = __fmaf_rn(xr[j*4+3], v3.w, a3);
        }
        accs[b * 4 + 0] = a0; accs[b * 4 + 1] = a1;
        accs[b * 4 + 2] = a2; accs[b * 4 + 3] = a3;
    }
    #pragma unroll
    for (int o = 16; o > 0; o >>= 1) {
        #pragma unroll
        for (int s = 0; s < 8; s++)
            accs[s] += __shfl_xor_sync(FULL, accs[s], o);
    }

    // exact reference-rounded distances + argmin with lowest-index tie-break
    float bd = 3.4e38f; int bi = 0x7fffffff;
    #pragma unroll
    for (int s = 0; s < 8; s++) {
        float dd = __fsub_rn(__fadd_rn(xn, g_wnorm[cand[s]]), 2.0f * accs[s]);
        if (dd < bd || (dd == bd && cand[s] < bi)) { bd = dd; bi = cand[s]; }
    }

    // fused epilogue: quantized_st + loss + histogram (all lanes agree on bi)
    const float* wv = W + (size_t)bi * D_DIM;
    float s = 0.f;
    #pragma unroll
    for (int j = 0; j < 4; j++) {
        float4 qv = *(const float4*)(wv + j * 128 + lane * 4);
        float dx = __fsub_rn(qv.x, xr[j * 4 + 0]);
        float dy = __fsub_rn(qv.y, xr[j * 4 + 1]);
        float dz = __fsub_rn(qv.z, xr[j * 4 + 2]);
        float dw = __fsub_rn(qv.w, xr[j * 4 + 3]);
        float4 st;
        st.x = __fadd_rn(xr[j * 4 + 0], dx);
        st.y = __fadd_rn(xr[j * 4 + 1], dy);
        st.z = __fadd_rn(xr[j * 4 + 2], dz);
        st.w = __fadd_rn(xr[j * 4 + 3], dw);
        *(float4*)(out_q + (size_t)token * D_DIM + j * 128 + lane * 4) = st;
        s += dx * dx + dy * dy + dz * dz + dw * dw;
    }
    #pragma unroll
    for (int o = 16; o > 0; o >>= 1) s += __shfl_xor_sync(FULL, s, o);
    if (lane == 0) {
        g_indices[token] = bi;
        if (write_loss) out_loss[token] = 1.25f * s * (1.0f / D_DIM);
        if (write_idx)  out_idx[token] = (float)bi;
        atomicAdd(&g_counts[bi], 1);
    }
}

// ---------------- zero counts / perplexity ----------------
__global__ void zero_counts_kernel() {
    int i = blockIdx.x * blockDim.x + threadIdx.x;
    if (i < K_CODES) g_counts[i] = 0;
}
__global__ void perplexity_kernel(float* __restrict__ out_perp, int M) {
    __shared__ float ws[32];
    float inv = 1.0f / (float)M;
    float s = 0.f;
    for (int i = threadIdx.x; i < K_CODES; i += blockDim.x) {
        float p = (float)g_counts[i] * inv;
        s += p * logf(p + 1e-10f);
    }
    #pragma unroll
    for (int o = 16; o > 0; o >>= 1) s += __shfl_down_sync(0xffffffffu, s, o);
    if ((threadIdx.x & 31) == 0) ws[threadIdx.x >> 5] = s;
    __syncthreads();
    if (threadIdx.x == 0) {
        float tot = 0.f;
        int nw = blockDim.x >> 5;
        for (int w = 0; w < nw; w++) tot += ws[w];
        *out_perp = expf(-tot);
    }
}

// ---------------- launch ----------------
extern "C" void kernel_launch(void* const* d_in, const int* in_sizes, int n_in,
                              void* d_out, int out_size)
{
    const float* X = (const float*)d_in[0];   // flat_input [32768, 512]
    const float* W = (const float*)d_in[1];   // weight [4096, 512]
    const int M = in_sizes[0] / D_DIM;

    float* out = (float*)d_out;
    float* out_q = out;
    size_t base = (size_t)M * D_DIM;
    int has_loss = out_size >= (int)(base + M);
    int has_perp = out_size >= (int)(base + M + 1);
    int has_idx  = out_size >= (int)(base + 2 * M + 1);
    float* out_loss = out + base;
    float* out_perp = out_loss + M;
    float* out_idx  = out_perp + 1;

    int nsm = 148;
    cudaDeviceGetAttribute(&nsm, cudaDevAttrMultiProcessorCount, 0);
    if (nsm <= 0) nsm = 148;

    cudaFuncSetAttribute(stage1_kernel, cudaFuncAttributeMaxDynamicSharedMemorySize, S_TOT);
    cudaFuncSetAttribute(cvtnorm_kernel, cudaFuncAttributeMaxDynamicSharedMemorySize,
                         64 * 513 * 4);

    cvtnorm_kernel<<<M / 64, 256, 64 * 513 * 4>>>(X, 1, SX);       // X -> fp8 + xnorm + aug
    cvtnorm_kernel<<<K_CODES / 64, 256, 64 * 513 * 4>>>(W, 0, SW); // W -> fp8 + wnorm + aug
    zero_counts_kernel<<<(K_CODES + 255) / 256, 256>>>();
    stage1_kernel<<<nsm, 512, S_TOT>>>();
    stage2_kernel<<<M / 8, 256>>>(X, W, out_q,
                                  has_loss ? out_loss : out_q,
                                  has_idx ? out_idx : out_q,
                                  has_loss, has_idx);
    if (has_perp) perplexity_kernel<<<1, 1024>>>(out_perp, M);
}

// round 16
// speedup vs baseline: 1.0615x; 1.0535x over previous
#include <cuda_runtime.h>
#include <math.h>
#include <stdint.h>

#define D_DIM 512
#define ROWB 544            // padded row: 512 fp8 + 32B aug chunk
#define K_CODES 4096
#define N_TOK 32768
#define NITEM 4096          // 256 m-tiles x 16 supertiles (256 codes each)

// fp8 quantization scales (validated R8-R15)
#define SX 32.0f
#define SW 131072.0f

// ---------------- device scratch (no allocations allowed) ----------------
__device__ int     g_indices[N_TOK];
__device__ int     g_counts[K_CODES];
__device__ float   g_wnorm[K_CODES];
__device__ float   g_xnorm[N_TOK];
__device__ uint8_t g_Xq[(size_t)N_TOK * ROWB];     // e4m3, padded rows
__device__ uint8_t g_Wq[(size_t)K_CODES * ROWB];   // e4m3, padded rows
__device__ uint2   g_cand32[(size_t)N_TOK * 128];  // per (token, st, wn, q): top-2 packed keys

// ---------------- PTX helpers ----------------
__device__ __forceinline__ uint32_t smem_to_u32(const void* p) {
    uint32_t a;
    asm("{ .reg .u64 t; cvta.to.shared.u64 t, %1; cvt.u32.u64 %0, t; }" : "=r"(a) : "l"(p));
    return a;
}
#define LDSM_X4(r0, r1, r2, r3, addr) \
    asm volatile("ldmatrix.sync.aligned.m8n8.x4.shared.b16 {%0,%1,%2,%3}, [%4];" \
        : "=r"(r0), "=r"(r1), "=r"(r2), "=r"(r3) : "r"(addr))
#define MMA16832_FP8(d, a, b0, b1) \
    asm volatile("mma.sync.aligned.m16n8k32.row.col.f32.e4m3.e4m3.f32 " \
        "{%0,%1,%2,%3},{%4,%5,%6,%7},{%8,%9},{%0,%1,%2,%3};" \
        : "+f"((d)[0]), "+f"((d)[1]), "+f"((d)[2]), "+f"((d)[3]) \
        : "r"((a)[0]), "r"((a)[1]), "r"((a)[2]), "r"((a)[3]), "r"(b0), "r"(b1))
#define CP_ASYNC16(dst, src) \
    asm volatile("cp.async.cg.shared.global [%0], [%1], 16;" :: "r"(dst), "l"(src))
#define CP_COMMIT() asm volatile("cp.async.commit_group;" ::: "memory")
#define CP_WAIT0()  asm volatile("cp.async.wait_group 0;" ::: "memory")

__device__ __forceinline__ uint16_t pack_e4m3x2(float hi, float lo) {
    uint16_t r;
    asm("cvt.rn.satfinite.e4m3x2.f32 %0, %1, %2;" : "=h"(r) : "f"(hi), "f"(lo));
    return r;
}

// dynamic smem layout for stage1 (bytes)
#define S_A     0                      // 64 KB A main (128 x 512B, swizzled)
#define S_AUGA  65536                  // 4 KB A aug (128 x 32B)
#define S_B0    (S_AUGA + 4096)        // 32 KB
#define S_B1    (S_B0 + 32768)         // 32 KB
#define S_AGB0  (S_B1 + 32768)         // 8 KB B aug (256 x 32B)
#define S_AGB1  (S_AGB0 + 8192)        // 8 KB
#define S_TOT   (S_AGB1 + 8192)        // 151552

// ---------------- fused prep: cvt + norm + aug (+ counts zero for W blocks) ----------------
// grid: [0, M/64) -> X blocks; [M/64, M/64 + K/64) -> W blocks
__global__ void prep_kernel(const float* __restrict__ X, const float* __restrict__ W,
                            int nxblk) {
    extern __shared__ float s[];               // [64][513]
    int which = (blockIdx.x < nxblk) ? 1 : 0;
    int r0 = (which ? blockIdx.x : (blockIdx.x - nxblk)) * 64;
    const float* src = which ? X : W;
    float scale = which ? SX : SW;

    const float4* g4 = (const float4*)(src + (size_t)r0 * D_DIM);
    for (int u = threadIdx.x; u < 64 * 128; u += 256) {
        int row = u >> 7, c4 = u & 127;
        float4 v = g4[(size_t)row * 128 + c4];
        float* p = s + row * 513 + c4 * 4;
        p[0] = v.x; p[1] = v.y; p[2] = v.z; p[3] = v.w;
    }
    __syncthreads();
    uint32_t* dst = (uint32_t*)(which ? (void*)g_Xq : (void*)g_Wq) + (size_t)r0 * (ROWB / 4);
    for (int i = threadIdx.x; i < 64 * 128; i += 256) {
        int row = i >> 7, c4 = i & 127;
        const float* p = s + row * 513 + c4 * 4;
        uint32_t lo = pack_e4m3x2(p[1] * scale, p[0] * scale);
        uint32_t hi = pack_e4m3x2(p[3] * scale, p[2] * scale);
        dst[(size_t)row * (ROWB / 4) + c4] = lo | (hi << 16);
    }
    // zero aug slots 1..7
    for (int i = threadIdx.x; i < 64 * 7; i += 256) {
        int row = i / 7, j = i % 7;
        dst[(size_t)row * (ROWB / 4) + 128 + 1 + j] = 0;
    }
    // W blocks also zero the histogram counts (4096 counts over 64 blocks)
    if (!which && threadIdx.x < 64) g_counts[r0 + threadIdx.x] = 0;
    // exact sequential norm per row (validated R3) + aug slot0
    // byte0: X=16 (0x58) / W=-wn*2^17 ; byte1: both 256 (0x78) -> +65536 bias per acc
    if (threadIdx.x < 64) {
        const float* p = s + threadIdx.x * 513;
        float acc = 0.f;
        #pragma unroll 8
        for (int i = 0; i < D_DIM; i++)
            acc = __fadd_rn(acc, __fmul_rn(p[i], p[i]));
        uint32_t augw;
        if (which) { g_xnorm[r0 + threadIdx.x] = acc; augw = 0x58u | (0x78u << 8); }
        else {
            g_wnorm[r0 + threadIdx.x] = acc;
            augw = (uint32_t)(pack_e4m3x2(0.f, -acc * 131072.f) & 0xFFu) | (0x78u << 8);
        }
        dst[(size_t)threadIdx.x * (ROWB / 4) + 128] = augw;
    }
}

// ---------------- stage1 cp.async loaders ----------------
__device__ __forceinline__ void issue_main(uint32_t sb, int tid, int st, int kc, int buf) {
    const uint8_t* src = g_Wq + (size_t)(st * 256) * ROWB + kc * 128;
    uint32_t bufaddr = sb + (buf ? S_B1 : S_B0);
    #pragma unroll
    for (int i = 0; i < 4; i++) {
        int unit = i * 512 + tid;               // 2048 16B units
        int nrow = unit >> 3, u = unit & 7;
        uint32_t dst = bufaddr + nrow * 128 + ((u ^ (nrow & 7)) << 4);
        CP_ASYNC16(dst, src + (size_t)nrow * ROWB + u * 16);
    }
    CP_COMMIT();
}
__device__ __forceinline__ void issue_aug(uint32_t sb, int tid, int st) {
    const uint8_t* src = g_Wq + (size_t)(st * 256) * ROWB + 512;
    uint32_t bufaddr = sb + ((st & 1) ? S_AGB1 : S_AGB0);
    int nrow = tid >> 1, u = tid & 1;
    CP_ASYNC16(bufaddr + nrow * 32 + u * 16, src + (size_t)nrow * ROWB + u * 16);
    CP_COMMIT();
}

__global__ void __launch_bounds__(512, 1) stage1_kernel() {
    extern __shared__ char smem[];
    const uint32_t sb = smem_to_u32(smem);
    const int tid = threadIdx.x;
    const int lane = tid & 31;
    const int w = tid >> 5;                // 16 warps
    const int wm = w & 3, wn = w >> 2;     // warp tile: rows wm*32, cols wn*64
    const unsigned FULL = 0xffffffffu;

    // static balanced item split (item = 1 supertile: 128 rows x 256 codes)
    const int G = gridDim.x, cta = blockIdx.x;
    const int qq = NITEM / G, rr = NITEM - qq * G;
    const int start = cta * qq + (cta < rr ? cta : rr);
    const int count = qq + (cta < rr ? 1 : 0);

    // per-lane ldmatrix addressing, XOR-periodic precompute
    const int a_row = (lane & 7) + ((lane >> 3) & 1) * 8;
    const int a_kh  = (lane >> 4) & 1;
    uint32_t apre[2][4], a_aug[2];
    #pragma unroll
    for (int mt = 0; mt < 2; mt++) {
        int r = wm * 32 + mt * 16 + a_row;
        uint32_t base = sb + S_A + r * 512;
        int ax = r & 7;
        #pragma unroll
        for (int s = 0; s < 4; s++)
            apre[mt][s] = base + ((uint32_t)((s * 2 + a_kh) ^ ax) << 4);
        a_aug[mt] = sb + S_AUGA + r * 32 + a_kh * 16;
    }
    const int b_row_in = (lane & 7) + ((lane >> 4) & 1) * 8;
    const int b_kh     = (lane >> 3) & 1;
    uint32_t bofs[4][4], b_augoff[4];
    #pragma unroll
    for (int p = 0; p < 4; p++) {
        int nr = wn * 64 + p * 16 + b_row_in;
        int bx = nr & 7;
        #pragma unroll
        for (int s = 0; s < 4; s++)
            bofs[p][s] = nr * 128 + ((uint32_t)((s * 2 + b_kh) ^ bx) << 4);
        b_augoff[p] = nr * 32 + b_kh * 16;
    }
    const int tg = lane & 3, g8 = lane >> 2;

    int cur_m = -1;
    for (int itm = start; itm < start + count; itm++) {
        const int mt_tile = itm >> 4;
        const int st = itm & 15;
        const int m0 = mt_tile * 128;
        const int lbase = (itm - start) * 4;      // local chunk index base (buffer parity)

        if (itm == start) {                        // pipeline prologue (first chunk + aug)
            issue_main(sb, tid, st, 0, 0);
            issue_aug(sb, tid, st);
        }

        if (mt_tile != cur_m) {
            cur_m = mt_tile;
            __syncthreads();
            const uint8_t* Xr = g_Xq + (size_t)m0 * ROWB;
            #pragma unroll 4
            for (int ld = 0; ld < 8; ld++) {
                int unit = ld * 512 + tid;
                int r = unit >> 5, u = unit & 31;
                uint4 v = *(const uint4*)(Xr + (size_t)r * ROWB + u * 16);
                *(uint4*)(smem + S_A + r * 512 + ((u ^ (r & 7)) << 4)) = v;
            }
            if (tid < 256) {
                int r = tid >> 1, u = tid & 1;
                uint4 v = *(const uint4*)(Xr + (size_t)r * ROWB + 512 + u * 16);
                *(uint4*)(smem + S_AUGA + r * 32 + u * 16) = v;
            }
            __syncthreads();
        }

        float acc[2][8][4];
        #pragma unroll
        for (int mt = 0; mt < 2; mt++)
            #pragma unroll
            for (int nt = 0; nt < 8; nt++)
                #pragma unroll
                for (int e = 0; e < 4; e++) acc[mt][nt][e] = 0.f;

        for (int kc = 0; kc < 4; kc++) {
            const int lgc = lbase + kc;
            CP_WAIT0();
            __syncthreads();
            // issue next chunk (pipelined across item boundaries)
            if (lgc + 1 < count * 4) {
                int nk = kc + 1, nst = st;
                if (nk == 4) { nk = 0; nst = (itm + 1) & 15; }
                issue_main(sb, tid, nst, nk, (lgc + 1) & 1);
                if (nk == 0) issue_aug(sb, tid, nst);
            }
            const uint32_t bbuf = sb + ((lgc & 1) ? S_B1 : S_B0);
            const uint32_t kadd = (uint32_t)kc << 7;     // kc*128
            #pragma unroll
            for (int s = 0; s < 4; s++) {
                uint32_t a[2][4];
                #pragma unroll
                for (int mt = 0; mt < 2; mt++)
                    LDSM_X4(a[mt][0], a[mt][1], a[mt][2], a[mt][3], apre[mt][s] + kadd);
                #pragma unroll
                for (int p = 0; p < 4; p++) {
                    uint32_t r0, r1, r2, r3;
                    LDSM_X4(r0, r1, r2, r3, bbuf + bofs[p][s]);
                    MMA16832_FP8(acc[0][2 * p],     a[0], r0, r1);
                    MMA16832_FP8(acc[0][2 * p + 1], a[0], r2, r3);
                    MMA16832_FP8(acc[1][2 * p],     a[1], r0, r1);
                    MMA16832_FP8(acc[1][2 * p + 1], a[1], r2, r3);
                }
            }
        }

        // ---- aug k-step: folds (65536 - wn*2^21) into acc ----
        {
            const uint32_t augb = sb + ((st & 1) ? S_AGB1 : S_AGB0);
            uint32_t a[2][4];
            #pragma unroll
            for (int mt = 0; mt < 2; mt++)
                LDSM_X4(a[mt][0], a[mt][1], a[mt][2], a[mt][3], a_aug[mt]);
            #pragma unroll
            for (int p = 0; p < 4; p++) {
                uint32_t r0, r1, r2, r3;
                LDSM_X4(r0, r1, r2, r3, augb + b_augoff[p]);
                MMA16832_FP8(acc[0][2 * p],     a[0], r0, r1);
                MMA16832_FP8(acc[0][2 * p + 1], a[0], r2, r3);
                MMA16832_FP8(acc[1][2 * p],     a[1], r0, r1);
                MMA16832_FP8(acc[1][2 * p + 1], a[1], r2, r3);
            }
        }

        // ---- packed-key epilogue: top-2 (max) per 32-code quadrant ----
        // id (12 bits) == code: st<<8 | wn<<6 | q<<5 | nq<<3 | tg<<1 | e
        {
            const int idb0 = (st << 8) | (wn << 6) | (tg << 1);
            int v1[2][2][2], v2[2][2][2];    // [mt][h][q]
            #pragma unroll
            for (int mt = 0; mt < 2; mt++)
                #pragma unroll
                for (int h = 0; h < 2; h++)
                    #pragma unroll
                    for (int q = 0; q < 2; q++) {
                        v1[mt][h][q] = (int)0x80000000;
                        v2[mt][h][q] = (int)0x80000000;
                    }
            #pragma unroll
            for (int mt = 0; mt < 2; mt++)
                #pragma unroll
                for (int q = 0; q < 2; q++)
                    #pragma unroll
                    for (int nq = 0; nq < 4; nq++)
                        #pragma unroll
                        for (int h = 0; h < 2; h++)
                            #pragma unroll
                            for (int e = 0; e < 2; e++) {
                                int id = idb0 | (q << 5) | (nq << 3) | e;
                                int key = (__float_as_int(acc[mt][q * 4 + nq][h * 2 + e])
                                           & (int)0xFFFFF000) | id;
                                int t = min(v1[mt][h][q], key);
                                v1[mt][h][q] = max(v1[mt][h][q], key);
                                v2[mt][h][q] = max(v2[mt][h][q], t);
                            }
            // merge sorted pairs across tg (offs 1,2) + direct store
            #pragma unroll
            for (int mt = 0; mt < 2; mt++)
                #pragma unroll
                for (int h = 0; h < 2; h++)
                    #pragma unroll
                    for (int q = 0; q < 2; q++) {
                        int V1 = v1[mt][h][q], V2 = v2[mt][h][q];
                        #pragma unroll
                        for (int off = 1; off <= 2; off <<= 1) {
                            int u1 = __shfl_xor_sync(FULL, V1, off);
                            int u2 = __shfl_xor_sync(FULL, V2, off);
                            int mn = min(V1, u1);
                            V1 = max(V1, u1);
                            V2 = max(mn, max(V2, u2));
                        }
                        if (tg == 0) {
                            int token = m0 + wm * 32 + mt * 16 + h * 8 + g8;
                            g_cand32[(size_t)token * 128 + st * 8 + wn * 2 + q] =
                                make_uint2((uint32_t)V1, (uint32_t)V2);
                        }
                    }
        }
    }
}

// ---------------- stage 2 (fused): top-8 of 256, PARALLEL exact rescore + outputs ----------------
__global__ void __launch_bounds__(256) stage2_kernel(const float* __restrict__ X,
                                                     const float* __restrict__ W,
                                                     float* __restrict__ out_q,
                                                     float* __restrict__ out_loss,
                                                     float* __restrict__ out_idx,
                                                     int write_loss, int write_idx) {
    const int warp = threadIdx.x >> 5, lane = threadIdx.x & 31;
    const int token = blockIdx.x * 8 + warp;
    const unsigned FULL = 0xffffffffu;

    int k[8];
    #pragma unroll
    for (int j = 0; j < 4; j++) {
        uint2 c = g_cand32[(size_t)token * 128 + j * 32 + lane];
        k[2 * j]     = (int)c.x;
        k[2 * j + 1] = (int)c.y;
    }

    float xr[16];
    const float* x = X + (size_t)token * D_DIM;
    #pragma unroll
    for (int j = 0; j < 4; j++) {
        float4 v = *(const float4*)(x + j * 128 + lane * 4);
        xr[j * 4 + 0] = v.x; xr[j * 4 + 1] = v.y; xr[j * 4 + 2] = v.z; xr[j * 4 + 3] = v.w;
    }
    float xn = g_xnorm[token];

    // top-8 of 256 packed keys (validated depth; all codes distinct by construction)
    int cand[8];
    #pragma unroll
    for (int s = 0; s < 8; s++) {
        int lm = k[0];
        #pragma unroll
        for (int j = 1; j < 8; j++) lm = max(lm, k[j]);
        int m = lm;
        #pragma unroll
        for (int o = 16; o > 0; o >>= 1) m = max(m, __shfl_xor_sync(FULL, m, o));
        if (lm == m) {
            bool cns = false;
            #pragma unroll
            for (int j = 0; j < 8; j++)
                if (!cns && k[j] == m) { k[j] = (int)0x80000000; cns = true; }
        }
        cand[s] = m & 0xFFF;
    }

    // 8 exact fp32 dots, 2 batches of 4 PARALLEL accumulators (MLP=4 each)
    float accs[8];
    #pragma unroll
    for (int b = 0; b < 2; b++) {
        const float* w0 = W + (size_t)cand[b * 4 + 0] * D_DIM;
        const float* w1 = W + (size_t)cand[b * 4 + 1] * D_DIM;
        const float* w2 = W + (size_t)cand[b * 4 + 2] * D_DIM;
        const float* w3 = W + (size_t)cand[b * 4 + 3] * D_DIM;
        float a0 = 0.f, a1 = 0.f, a2 = 0.f, a3 = 0.f;
        #pragma unroll
        for (int j = 0; j < 4; j++) {
            int off = j * 128 + lane * 4;
            float4 v0 = *(const float4*)(w0 + off);
            float4 v1 = *(const float4*)(w1 + off);
            float4 v2 = *(const float4*)(w2 + off);
            float4 v3 = *(const float4*)(w3 + off);
            a0 = __fmaf_rn(xr[j*4+0], v0.x, a0); a0 = __fmaf_rn(xr[j*4+1], v0.y, a0);
            a0 = __fmaf_rn(xr[j*4+2], v0.z, a0); a0 = __fmaf_rn(xr[j*4+3], v0.w, a0);
            a1 = __fmaf_rn(xr[j*4+0], v1.x, a1); a1 = __fmaf_rn(xr[j*4+1], v1.y, a1);
            a1 = __fmaf_rn(xr[j*4+2], v1.z, a1); a1 = __fmaf_rn(xr[j*4+3], v1.w, a1);
            a2 = __fmaf_rn(xr[j*4+0], v2.x, a2); a2 = __fmaf_rn(xr[j*4+1], v2.y, a2);
            a2 = __fmaf_rn(xr[j*4+2], v2.z, a2); a2 = __fmaf_rn(xr[j*4+3], v2.w, a2);
            a3 = __fmaf_rn(xr[j*4+0], v3.x, a3); a3 = __fmaf_rn(xr[j*4+1], v3.y, a3);
            a3 = __fmaf_rn(xr[j*4+2], v3.z, a3); a3 = __fmaf_rn(xr[j*4+3], v3.w, a3);
        }
        accs[b * 4 + 0] = a0; accs[b * 4 + 1] = a1;
        accs[b * 4 + 2] = a2; accs[b * 4 + 3] = a3;
    }
    #pragma unroll
    for (int o = 16; o > 0; o >>= 1) {
        #pragma unroll
        for (int s = 0; s < 8; s++)
            accs[s] += __shfl_xor_sync(FULL, accs[s], o);
    }

    // exact reference-rounded distances + argmin with lowest-index tie-break
    float bd = 3.4e38f; int bi = 0x7fffffff;
    #pragma unroll
    for (int s = 0; s < 8; s++) {
        float dd = __fsub_rn(__fadd_rn(xn, g_wnorm[cand[s]]), 2.0f * accs[s]);
        if (dd < bd || (dd == bd && cand[s] < bi)) { bd = dd; bi = cand[s]; }
    }

    // fused epilogue: quantized_st + loss + histogram (all lanes agree on bi)
    const float* wv = W + (size_t)bi * D_DIM;
    float s = 0.f;
    #pragma unroll
    for (int j = 0; j < 4; j++) {
        float4 qv = *(const float4*)(wv + j * 128 + lane * 4);
        float dx = __fsub_rn(qv.x, xr[j * 4 + 0]);
        float dy = __fsub_rn(qv.y, xr[j * 4 + 1]);
        float dz = __fsub_rn(qv.z, xr[j * 4 + 2]);
        float dw = __fsub_rn(qv.w, xr[j * 4 + 3]);
        float4 st;
        st.x = __fadd_rn(xr[j * 4 + 0], dx);
        st.y = __fadd_rn(xr[j * 4 + 1], dy);
        st.z = __fadd_rn(xr[j * 4 + 2], dz);
        st.w = __fadd_rn(xr[j * 4 + 3], dw);
        *(float4*)(out_q + (size_t)token * D_DIM + j * 128 + lane * 4) = st;
        s += dx * dx + dy * dy + dz * dz + dw * dw;
    }
    #pragma unroll
    for (int o = 16; o > 0; o >>= 1) s += __shfl_xor_sync(FULL, s, o);
    if (lane == 0) {
        g_indices[token] = bi;
        if (write_loss) out_loss[token] = 1.25f * s * (1.0f / D_DIM);
        if (write_idx)  out_idx[token] = (float)bi;
        atomicAdd(&g_counts[bi], 1);
    }
}

// ---------------- perplexity ----------------
__global__ void perplexity_kernel(float* __restrict__ out_perp, int M) {
    __shared__ float ws[32];
    float inv = 1.0f / (float)M;
    float s = 0.f;
    for (int i = threadIdx.x; i < K_CODES; i += blockDim.x) {
        float p = (float)g_counts[i] * inv;
        s += p * logf(p + 1e-10f);
    }
    #pragma unroll
    for (int o = 16; o > 0; o >>= 1) s += __shfl_down_sync(0xffffffffu, s, o);
    if ((threadIdx.x & 31) == 0) ws[threadIdx.x >> 5] = s;
    __syncthreads();
    if (threadIdx.x == 0) {
        float tot = 0.f;
        int nw = blockDim.x >> 5;
        for (int w = 0; w < nw; w++) tot += ws[w];
        *out_perp = expf(-tot);
    }
}

// ---------------- launch ----------------
extern "C" void kernel_launch(void* const* d_in, const int* in_sizes, int n_in,
                              void* d_out, int out_size)
{
    const float* X = (const float*)d_in[0];   // flat_input [32768, 512]
    const float* W = (const float*)d_in[1];   // weight [4096, 512]
    const int M = in_sizes[0] / D_DIM;

    float* out = (float*)d_out;
    float* out_q = out;
    size_t base = (size_t)M * D_DIM;
    int has_loss = out_size >= (int)(base + M);
    int has_perp = out_size >= (int)(base + M + 1);
    int has_idx  = out_size >= (int)(base + 2 * M + 1);
    float* out_loss = out + base;
    float* out_perp = out_loss + M;
    float* out_idx  = out_perp + 1;

    int nsm = 148;
    cudaDeviceGetAttribute(&nsm, cudaDevAttrMultiProcessorCount, 0);
    if (nsm <= 0) nsm = 148;

    cudaFuncSetAttribute(stage1_kernel, cudaFuncAttributeMaxDynamicSharedMemorySize, S_TOT);
    cudaFuncSetAttribute(prep_kernel, cudaFuncAttributeMaxDynamicSharedMemorySize,
                         64 * 513 * 4);

    int nxblk = M / 64;
    prep_kernel<<<nxblk + K_CODES / 64, 256, 64 * 513 * 4>>>(X, W, nxblk);
    stage1_kernel<<<nsm, 512, S_TOT>>>();
    stage2_kernel<<<M / 8, 256>>>(X, W, out_q,
                                  has_loss ? out_loss : out_q,
                                  has_idx ? out_idx : out_q,
                                  has_loss, has_idx);
    if (has_perp) perplexity_kernel<<<1, 1024>>>(out_perp, M);
}